// round 5
// baseline (speedup 1.0000x reference)
#include <cuda_runtime.h>
#include <cstdint>

// ---------------------------------------------------------------------------
// PointNet++ encoder: 32 batches (4*8) x 4096 points x 3.
// Stage1: FPS->256, ball r=0.2 k=32, MLP 3->64->64->128, max
// Stage2: FPS->128, ball r=0.4 k=32, MLP 131->128->128->256, max
// Stage3: group-all 128 pts, MLP 259->256->512->1024, max -> (32,1024)
// ---------------------------------------------------------------------------

#define BB   32      // flattened batch (4*8)
#define N1   4096
#define S1   256
#define S2   128
#define NS   32      // nsample

// Scratch (static device globals -- no allocation anywhere)
__device__ float g_scr0[262144 * 128];   // 134 MB
__device__ float g_scr1[262144 * 128];   // 134 MB
__device__ float g_f1[BB * S1 * 128];
__device__ float g_f2[BB * S2 * 256];
__device__ float g_nx1[BB * S1 * 3];
__device__ float g_nx2[BB * S2 * 3];
__device__ int   g_g1[BB * S1 * NS];
__device__ int   g_g2[BB * S2 * NS];
__device__ float g_x3[BB * S2 * 259];

// ---------------------------------------------------------------------------
// Farthest point sampling. One block per batch. Points + running min-dist held
// in registers. Distance math uses __fmul_rn/__fadd_rn so results are bitwise
// identical to the reference (no FMA contraction). Argmax tie-break: lowest
// index first (packed key: value bits high, ~index low; take max).
// ---------------------------------------------------------------------------
template <int N, int NPTS, int THREADS>
__global__ void __launch_bounds__(THREADS) fps_kernel(
    const float* __restrict__ xyz_all, float* __restrict__ new_xyz)
{
    constexpr int PPT = N / THREADS;
    const int b = blockIdx.x;
    const int t = threadIdx.x;
    const float* xyz = xyz_all + (size_t)b * N * 3;

    float px[PPT], py[PPT], pz[PPT], md[PPT];
#pragma unroll
    for (int j = 0; j < PPT; j++) {
        int i = t + j * THREADS;
        px[j] = xyz[i * 3 + 0];
        py[j] = xyz[i * 3 + 1];
        pz[j] = xyz[i * 3 + 2];
        md[j] = 1e10f;
    }

    __shared__ unsigned long long wred[THREADS / 32];
    __shared__ int s_last;

    int last = 0;
    for (int it = 0; it < NPTS; it++) {
        float lx = __ldg(&xyz[last * 3 + 0]);
        float ly = __ldg(&xyz[last * 3 + 1]);
        float lz = __ldg(&xyz[last * 3 + 2]);
        if (t == 0) {
            float* o = new_xyz + (size_t)(b * NPTS + it) * 3;
            o[0] = lx; o[1] = ly; o[2] = lz;
        }
        unsigned long long best = 0ull;
#pragma unroll
        for (int j = 0; j < PPT; j++) {
            float dx = px[j] - lx, dy = py[j] - ly, dz = pz[j] - lz;
            float d = __fadd_rn(__fadd_rn(__fmul_rn(dx, dx), __fmul_rn(dy, dy)),
                                __fmul_rn(dz, dz));
            float m = fminf(md[j], d);
            md[j] = m;
            unsigned long long key =
                (((unsigned long long)__float_as_uint(m)) << 32) |
                (unsigned)(0xFFFFFFFFu - (unsigned)(t + j * THREADS));
            best = (key > best) ? key : best;
        }
#pragma unroll
        for (int off = 16; off > 0; off >>= 1) {
            unsigned long long o = __shfl_down_sync(0xffffffffu, best, off);
            best = (o > best) ? o : best;
        }
        if ((t & 31) == 0) wred[t >> 5] = best;
        __syncthreads();
        if (t < 32) {
            unsigned long long v = (t < THREADS / 32) ? wred[t] : 0ull;
#pragma unroll
            for (int off = 16; off > 0; off >>= 1) {
                unsigned long long o = __shfl_down_sync(0xffffffffu, v, off);
                v = (o > v) ? o : v;
            }
            if (t == 0)
                s_last = (int)(0xFFFFFFFFu - (unsigned)(v & 0xFFFFFFFFull));
        }
        __syncthreads();
        last = s_last;
    }
}

// ---------------------------------------------------------------------------
// Ball query: one warp per center. Scans points in ascending index order,
// ballot+popc compaction collects the first 32 indices with d2 < R2 (strict),
// pads with the first found index -- exactly the reference's sort+pad.
// ---------------------------------------------------------------------------
template <int N>
__global__ void __launch_bounds__(256) ballq_kernel(
    const float* __restrict__ xyz_all, const float* __restrict__ centers,
    int S, float R2, int* __restrict__ out)
{
    const int gw = (blockIdx.x * blockDim.x + threadIdx.x) >> 5;
    const int lane = threadIdx.x & 31;
    const int wl = threadIdx.x >> 5;
    __shared__ int buf[8][32];

    const int b = gw / S;
    const float* xyz = xyz_all + (size_t)b * N * 3;
    const float cx = centers[gw * 3 + 0];
    const float cy = centers[gw * 3 + 1];
    const float cz = centers[gw * 3 + 2];

    int cnt = 0;
    for (int base = 0; base < N; base += 32) {
        int p = base + lane;
        float dx = xyz[p * 3 + 0] - cx;
        float dy = xyz[p * 3 + 1] - cy;
        float dz = xyz[p * 3 + 2] - cz;
        float d2 = __fadd_rn(__fadd_rn(__fmul_rn(dx, dx), __fmul_rn(dy, dy)),
                             __fmul_rn(dz, dz));
        bool pred = d2 < R2;
        unsigned mask = __ballot_sync(0xffffffffu, pred);
        if (pred) {
            int pos = cnt + __popc(mask & ((1u << lane) - 1u));
            if (pos < NS) buf[wl][pos] = p;
        }
        cnt += __popc(mask);
        if (cnt >= NS) break;
    }
    __syncwarp();
    int nv = cnt < NS ? cnt : NS;
    int first = (cnt > 0) ? buf[wl][0] : 0;
    int val = (lane < nv) ? buf[wl][lane] : first;
    out[(size_t)gw * NS + lane] = val;
}

// ---------------------------------------------------------------------------
// Gather kernels
// ---------------------------------------------------------------------------
__global__ void gather1_kernel(const float* __restrict__ data,
                               float* __restrict__ x1)
{
    int r = blockIdx.x * blockDim.x + threadIdx.x;
    if (r >= BB * S1 * NS) return;
    int c = r >> 5;            // center index (b*S1+s)
    int b = c >> 8;            // /256
    int g = g_g1[r];
    const float* p = data + ((size_t)b * N1 + g) * 3;
    const float* ctr = g_nx1 + (size_t)c * 3;
    float* o = x1 + (size_t)r * 3;
    o[0] = p[0] - ctr[0];
    o[1] = p[1] - ctr[1];
    o[2] = p[2] - ctr[2];
}

__global__ void gather2_kernel(float* __restrict__ x2)
{
    int r = blockIdx.x * 4 + (threadIdx.x >> 5);   // row in [0, 131072)
    int lane = threadIdx.x & 31;
    int c = r >> 5;            // center (b*S2+s)
    int b = c >> 7;            // /128
    int j = g_g2[r];
    const float* src = g_nx1 + ((size_t)b * S1 + j) * 3;
    const float* ctr = g_nx2 + (size_t)c * 3;
    const float* f = g_f1 + ((size_t)b * S1 + j) * 128;
    float* dst = x2 + (size_t)r * 131;
    for (int col = lane; col < 131; col += 32)
        dst[col] = (col < 3) ? (src[col] - ctr[col]) : f[col - 3];
}

__global__ void concat3_kernel(float* __restrict__ x3)
{
    int t = blockIdx.x * blockDim.x + threadIdx.x;
    if (t >= BB * S2 * 259) return;
    int r = t / 259, col = t - r * 259;
    x3[t] = (col < 3) ? g_nx2[(size_t)r * 3 + col]
                      : g_f2[(size_t)r * 256 + (col - 3)];
}

// ---------------------------------------------------------------------------
// GEMM: C[M,N] = relu(A[M,K] @ W[N,K]^T + bias). 128x64 tile, BK=16,
// 8x4 register micro-tile, 256 threads. M % 128 == 0, N % 64 == 0, K free.
// ---------------------------------------------------------------------------
__global__ void __launch_bounds__(256) gemm_bias_relu(
    const float* __restrict__ A, const float* __restrict__ W,
    const float* __restrict__ bias, float* __restrict__ C,
    int M, int N, int K, int lda)
{
    __shared__ float As[16][128];
    __shared__ float Ws[16][64];
    const int tid = threadIdx.x;
    const int ty = tid >> 4, tx = tid & 15;
    const int m0 = blockIdx.x * 128;
    const int n0 = blockIdx.y * 64;

    const int a_m = tid >> 1;
    const int a_k0 = (tid & 1) * 8;
    const int w_n = tid >> 2;
    const int w_k0 = (tid & 3) * 4;

    const float* Arow = A + (size_t)(m0 + a_m) * lda;
    const float* Wrow = W + (size_t)(n0 + w_n) * K;

    float acc[8][4];
#pragma unroll
    for (int i = 0; i < 8; i++)
#pragma unroll
        for (int j = 0; j < 4; j++) acc[i][j] = 0.f;

    for (int k0 = 0; k0 < K; k0 += 16) {
#pragma unroll
        for (int i = 0; i < 8; i++) {
            int k = k0 + a_k0 + i;
            As[a_k0 + i][a_m] = (k < K) ? Arow[k] : 0.f;
        }
#pragma unroll
        for (int i = 0; i < 4; i++) {
            int k = k0 + w_k0 + i;
            Ws[w_k0 + i][w_n] = (k < K) ? Wrow[k] : 0.f;
        }
        __syncthreads();
#pragma unroll
        for (int kk = 0; kk < 16; kk++) {
            float a[8], wv[4];
#pragma unroll
            for (int i = 0; i < 8; i++) a[i] = As[kk][ty * 8 + i];
#pragma unroll
            for (int j = 0; j < 4; j++) wv[j] = Ws[kk][tx * 4 + j];
#pragma unroll
            for (int i = 0; i < 8; i++)
#pragma unroll
                for (int j = 0; j < 4; j++)
                    acc[i][j] = fmaf(a[i], wv[j], acc[i][j]);
        }
        __syncthreads();
    }

    float bv[4];
#pragma unroll
    for (int j = 0; j < 4; j++) bv[j] = bias[n0 + tx * 4 + j];
#pragma unroll
    for (int i = 0; i < 8; i++) {
        int m = m0 + ty * 8 + i;
        float4 o;
        o.x = fmaxf(acc[i][0] + bv[0], 0.f);
        o.y = fmaxf(acc[i][1] + bv[1], 0.f);
        o.z = fmaxf(acc[i][2] + bv[2], 0.f);
        o.w = fmaxf(acc[i][3] + bv[3], 0.f);
        *reinterpret_cast<float4*>(C + (size_t)m * N + n0 + tx * 4) = o;
    }
}

// ---------------------------------------------------------------------------
// Max-pools
// ---------------------------------------------------------------------------
__global__ void maxpool_k_kernel(const float* __restrict__ src,
                                 float* __restrict__ dst, int nc, int C)
{
    int t = blockIdx.x * blockDim.x + threadIdx.x;
    if (t >= nc * C) return;
    int o = t % C, c = t / C;
    const float* p = src + (size_t)c * NS * C + o;
    float m = p[0];
#pragma unroll 4
    for (int k = 1; k < NS; k++) m = fmaxf(m, p[(size_t)k * C]);
    dst[t] = m;
}

__global__ void finalpool_kernel(const float* __restrict__ src,
                                 float* __restrict__ out)
{
    int t = blockIdx.x * blockDim.x + threadIdx.x;
    if (t >= BB * 1024) return;
    int b = t >> 10, o = t & 1023;
    const float* p = src + (size_t)b * S2 * 1024 + o;
    float m = p[0];
    for (int k = 1; k < S2; k++) m = fmaxf(m, p[(size_t)k * 1024]);
    out[t] = m;
}

// ---------------------------------------------------------------------------
static void run_gemm(const float* A, const float* W, const float* bias,
                     float* C, int M, int N, int K, int lda)
{
    dim3 g(M / 128, N / 64);
    gemm_bias_relu<<<g, 256>>>(A, W, bias, C, M, N, K, lda);
}

extern "C" void kernel_launch(void* const* d_in, const int* in_sizes, int n_in,
                              void* d_out, int out_size)
{
    (void)in_sizes; (void)n_in; (void)out_size;
    const float* data = (const float*)d_in[0];
    const float *w[9], *bi[9];
    for (int i = 0; i < 9; i++) {
        w[i]  = (const float*)d_in[1 + 2 * i];
        bi[i] = (const float*)d_in[2 + 2 * i];
    }

    float *scr0, *scr1, *f1, *f2, *nx1, *nx2, *x3;
    int *g1, *g2;
    cudaGetSymbolAddress((void**)&scr0, g_scr0);
    cudaGetSymbolAddress((void**)&scr1, g_scr1);
    cudaGetSymbolAddress((void**)&f1, g_f1);
    cudaGetSymbolAddress((void**)&f2, g_f2);
    cudaGetSymbolAddress((void**)&nx1, g_nx1);
    cudaGetSymbolAddress((void**)&nx2, g_nx2);
    cudaGetSymbolAddress((void**)&g1, g_g1);
    cudaGetSymbolAddress((void**)&g2, g_g2);
    cudaGetSymbolAddress((void**)&x3, g_x3);

    const float R2a = (float)(0.2 * 0.2);   // match JAX weak-typed f32 cast
    const float R2b = (float)(0.4 * 0.4);

    // ---- Stage 1 ----
    fps_kernel<N1, S1, 512><<<BB, 512>>>(data, nx1);
    ballq_kernel<N1><<<(BB * S1) / 8, 256>>>(data, nx1, S1, R2a, g1);
    gather1_kernel<<<(BB * S1 * NS + 255) / 256, 256>>>(data, scr1);
    run_gemm(scr1, w[0], bi[0], scr0, BB * S1 * NS, 64, 3, 3);
    run_gemm(scr0, w[1], bi[1], scr1, BB * S1 * NS, 64, 64, 64);
    run_gemm(scr1, w[2], bi[2], scr0, BB * S1 * NS, 128, 64, 64);
    maxpool_k_kernel<<<(BB * S1 * 128 + 255) / 256, 256>>>(scr0, f1, BB * S1, 128);

    // ---- Stage 2 ----
    fps_kernel<S1, S2, 256><<<BB, 256>>>(nx1, nx2);
    ballq_kernel<S1><<<(BB * S2) / 8, 256>>>(nx1, nx2, S2, R2b, g2);
    gather2_kernel<<<(BB * S2 * NS) / 4, 128>>>(scr0);
    run_gemm(scr0, w[3], bi[3], scr1, BB * S2 * NS, 128, 131, 131);
    run_gemm(scr1, w[4], bi[4], scr0, BB * S2 * NS, 128, 128, 128);
    run_gemm(scr0, w[5], bi[5], scr1, BB * S2 * NS, 256, 128, 128);
    maxpool_k_kernel<<<(BB * S2 * 256 + 255) / 256, 256>>>(scr1, f2, BB * S2, 256);

    // ---- Stage 3 (group-all) ----
    concat3_kernel<<<(BB * S2 * 259 + 255) / 256, 256>>>(x3);
    run_gemm(x3, w[6], bi[6], scr0, BB * S2, 256, 259, 259);
    run_gemm(scr0, w[7], bi[7], scr1, BB * S2, 512, 256, 256);
    run_gemm(scr1, w[8], bi[8], scr0, BB * S2, 1024, 512, 512);
    finalpool_kernel<<<(BB * 1024 + 255) / 256, 256>>>(scr0, (float*)d_out);
}

// round 7
// speedup vs baseline: 1.3950x; 1.3950x over previous
#include <cuda_runtime.h>
#include <cstdint>

// ---------------------------------------------------------------------------
// PointNet++ encoder on GB300 (compiled for base sm_103: NO tcgen05, NO wgmma).
// FPS / ball-query / gathers: exact fp32 (bitwise-match indices vs JAX ref).
// MLP layers K>=32: mma.sync m16n8k8 tf32 with 3-term fp32 emulation.
// Layer 1_0 (K=3): classic SGEMM (memory-bound).
// ---------------------------------------------------------------------------

#define BB   32
#define N1   4096
#define S1   256
#define S2   128
#define NS   32

// Scratch (static device globals -- no allocation anywhere)
__device__ float g_scr0[262144 * 128];   // 134 MB
__device__ float g_scr1[262144 * 128];   // 134 MB
__device__ float g_f1[BB * S1 * 128];
__device__ float g_f2[BB * S2 * 256];
__device__ float g_nx1[BB * S1 * 3];
__device__ float g_nx2[BB * S2 * 3];
__device__ int   g_g1[BB * S1 * NS];
__device__ int   g_g2[BB * S2 * NS];
__device__ float g_x3[BB * S2 * 288];
__device__ float g_w2p[128 * 160];
__device__ float g_w3p[256 * 288];

__device__ __forceinline__ float tf32r(float x) {
    float r;
    asm("cvt.rna.tf32.f32 %0, %1;" : "=f"(r) : "f"(x));
    return r;
}

#define MMA_TF32(c, a, b0, b1)                                                \
    asm volatile(                                                             \
        "mma.sync.aligned.m16n8k8.row.col.f32.tf32.tf32.f32 "                 \
        "{%0,%1,%2,%3}, {%4,%5,%6,%7}, {%8,%9}, {%0,%1,%2,%3};"               \
        : "+f"((c)[0]), "+f"((c)[1]), "+f"((c)[2]), "+f"((c)[3])              \
        : "r"((a)[0]), "r"((a)[1]), "r"((a)[2]), "r"((a)[3]),                 \
          "r"(b0), "r"(b1))

// ---------------------------------------------------------------------------
// FPS (bitwise exact vs reference)
// ---------------------------------------------------------------------------
template <int N, int NPTS, int THREADS>
__global__ void __launch_bounds__(THREADS) fps_kernel(
    const float* __restrict__ xyz_all, float* __restrict__ new_xyz)
{
    constexpr int PPT = N / THREADS;
    const int b = blockIdx.x;
    const int t = threadIdx.x;
    const float* xyz = xyz_all + (size_t)b * N * 3;

    float px[PPT], py[PPT], pz[PPT], md[PPT];
#pragma unroll
    for (int j = 0; j < PPT; j++) {
        int i = t + j * THREADS;
        px[j] = xyz[i * 3 + 0];
        py[j] = xyz[i * 3 + 1];
        pz[j] = xyz[i * 3 + 2];
        md[j] = 1e10f;
    }

    __shared__ unsigned long long wred[THREADS / 32];
    __shared__ int s_last;

    int last = 0;
    for (int it = 0; it < NPTS; it++) {
        float lx = __ldg(&xyz[last * 3 + 0]);
        float ly = __ldg(&xyz[last * 3 + 1]);
        float lz = __ldg(&xyz[last * 3 + 2]);
        if (t == 0) {
            float* o = new_xyz + (size_t)(b * NPTS + it) * 3;
            o[0] = lx; o[1] = ly; o[2] = lz;
        }
        unsigned long long best = 0ull;
#pragma unroll
        for (int j = 0; j < PPT; j++) {
            float dx = px[j] - lx, dy = py[j] - ly, dz = pz[j] - lz;
            float d = __fadd_rn(__fadd_rn(__fmul_rn(dx, dx), __fmul_rn(dy, dy)),
                                __fmul_rn(dz, dz));
            float m = fminf(md[j], d);
            md[j] = m;
            unsigned long long key =
                (((unsigned long long)__float_as_uint(m)) << 32) |
                (unsigned)(0xFFFFFFFFu - (unsigned)(t + j * THREADS));
            best = (key > best) ? key : best;
        }
#pragma unroll
        for (int off = 16; off > 0; off >>= 1) {
            unsigned long long o = __shfl_down_sync(0xffffffffu, best, off);
            best = (o > best) ? o : best;
        }
        if ((t & 31) == 0) wred[t >> 5] = best;
        __syncthreads();
        if (t < 32) {
            unsigned long long v = (t < THREADS / 32) ? wred[t] : 0ull;
#pragma unroll
            for (int off = 16; off > 0; off >>= 1) {
                unsigned long long o = __shfl_down_sync(0xffffffffu, v, off);
                v = (o > v) ? o : v;
            }
            if (t == 0)
                s_last = (int)(0xFFFFFFFFu - (unsigned)(v & 0xFFFFFFFFull));
        }
        __syncthreads();
        last = s_last;
    }
}

// ---------------------------------------------------------------------------
// Ball query (exact)
// ---------------------------------------------------------------------------
template <int N>
__global__ void __launch_bounds__(256) ballq_kernel(
    const float* __restrict__ xyz_all, const float* __restrict__ centers,
    int S, float R2, int* __restrict__ out)
{
    const int gw = (blockIdx.x * blockDim.x + threadIdx.x) >> 5;
    const int lane = threadIdx.x & 31;
    const int wl = threadIdx.x >> 5;
    __shared__ int buf[8][32];

    const int b = gw / S;
    const float* xyz = xyz_all + (size_t)b * N * 3;
    const float cx = centers[gw * 3 + 0];
    const float cy = centers[gw * 3 + 1];
    const float cz = centers[gw * 3 + 2];

    int cnt = 0;
    for (int base = 0; base < N; base += 32) {
        int p = base + lane;
        float dx = xyz[p * 3 + 0] - cx;
        float dy = xyz[p * 3 + 1] - cy;
        float dz = xyz[p * 3 + 2] - cz;
        float d2 = __fadd_rn(__fadd_rn(__fmul_rn(dx, dx), __fmul_rn(dy, dy)),
                             __fmul_rn(dz, dz));
        bool pred = d2 < R2;
        unsigned mask = __ballot_sync(0xffffffffu, pred);
        if (pred) {
            int pos = cnt + __popc(mask & ((1u << lane) - 1u));
            if (pos < NS) buf[wl][pos] = p;
        }
        cnt += __popc(mask);
        if (cnt >= NS) break;
    }
    __syncwarp();
    int nv = cnt < NS ? cnt : NS;
    int first = (cnt > 0) ? buf[wl][0] : 0;
    int val = (lane < nv) ? buf[wl][lane] : first;
    out[(size_t)gw * NS + lane] = val;
}

// ---------------------------------------------------------------------------
// Gathers / concat / weight pads
// ---------------------------------------------------------------------------
__global__ void gather1_kernel(const float* __restrict__ data,
                               float* __restrict__ x1)
{
    int r = blockIdx.x * blockDim.x + threadIdx.x;
    if (r >= BB * S1 * NS) return;
    int c = r >> 5;
    int b = c >> 8;
    int g = g_g1[r];
    const float* p = data + ((size_t)b * N1 + g) * 3;
    const float* ctr = g_nx1 + (size_t)c * 3;
    float* o = x1 + (size_t)r * 3;
    o[0] = p[0] - ctr[0];
    o[1] = p[1] - ctr[1];
    o[2] = p[2] - ctr[2];
}

// rows padded to 160 cols (131 real + 29 zeros)
__global__ void gather2_kernel(float* __restrict__ x2)
{
    int r = blockIdx.x * 4 + (threadIdx.x >> 5);
    int lane = threadIdx.x & 31;
    int c = r >> 5;
    int b = c >> 7;
    int j = g_g2[r];
    const float* src = g_nx1 + ((size_t)b * S1 + j) * 3;
    const float* ctr = g_nx2 + (size_t)c * 3;
    const float* f = g_f1 + ((size_t)b * S1 + j) * 128;
    float* dst = x2 + (size_t)r * 160;
    for (int col = lane; col < 160; col += 32)
        dst[col] = (col < 3) ? (src[col] - ctr[col])
                             : (col < 131 ? f[col - 3] : 0.f);
}

// rows padded to 288 cols (259 real + 29 zeros)
__global__ void concat3_kernel(float* __restrict__ x3)
{
    int t = blockIdx.x * blockDim.x + threadIdx.x;
    if (t >= BB * S2 * 288) return;
    int r = t / 288, col = t - r * 288;
    x3[t] = (col < 3) ? g_nx2[(size_t)r * 3 + col]
                      : (col < 259 ? g_f2[(size_t)r * 256 + (col - 3)] : 0.f);
}

__global__ void padw_kernel(const float* __restrict__ w, float* __restrict__ o,
                            int n, int kin, int kout)
{
    int t = blockIdx.x * blockDim.x + threadIdx.x;
    if (t >= n * kout) return;
    int r = t / kout, c = t - r * kout;
    o[t] = (c < kin) ? w[r * kin + c] : 0.f;
}

// ---------------------------------------------------------------------------
// SGEMM for layer 1_0 (K=3, memory-bound)
// ---------------------------------------------------------------------------
__global__ void __launch_bounds__(256) gemm_bias_relu(
    const float* __restrict__ A, const float* __restrict__ W,
    const float* __restrict__ bias, float* __restrict__ C,
    int M, int N, int K, int lda)
{
    __shared__ float As[16][128];
    __shared__ float Ws[16][64];
    const int tid = threadIdx.x;
    const int ty = tid >> 4, tx = tid & 15;
    const int m0 = blockIdx.x * 128;
    const int n0 = blockIdx.y * 64;

    const int a_m = tid >> 1;
    const int a_k0 = (tid & 1) * 8;
    const int w_n = tid >> 2;
    const int w_k0 = (tid & 3) * 4;

    const float* Arow = A + (size_t)(m0 + a_m) * lda;
    const float* Wrow = W + (size_t)(n0 + w_n) * K;

    float acc[8][4];
#pragma unroll
    for (int i = 0; i < 8; i++)
#pragma unroll
        for (int j = 0; j < 4; j++) acc[i][j] = 0.f;

    for (int k0 = 0; k0 < K; k0 += 16) {
#pragma unroll
        for (int i = 0; i < 8; i++) {
            int k = k0 + a_k0 + i;
            As[a_k0 + i][a_m] = (k < K) ? Arow[k] : 0.f;
        }
#pragma unroll
        for (int i = 0; i < 4; i++) {
            int k = k0 + w_k0 + i;
            Ws[w_k0 + i][w_n] = (k < K) ? Wrow[k] : 0.f;
        }
        __syncthreads();
#pragma unroll
        for (int kk = 0; kk < 16; kk++) {
            float a[8], wv[4];
#pragma unroll
            for (int i = 0; i < 8; i++) a[i] = As[kk][ty * 8 + i];
#pragma unroll
            for (int j = 0; j < 4; j++) wv[j] = Ws[kk][tx * 4 + j];
#pragma unroll
            for (int i = 0; i < 8; i++)
#pragma unroll
                for (int j = 0; j < 4; j++)
                    acc[i][j] = fmaf(a[i], wv[j], acc[i][j]);
        }
        __syncthreads();
    }

    float bv[4];
#pragma unroll
    for (int j = 0; j < 4; j++) bv[j] = bias[n0 + tx * 4 + j];
#pragma unroll
    for (int i = 0; i < 8; i++) {
        int m = m0 + ty * 8 + i;
        float4 o;
        o.x = fmaxf(acc[i][0] + bv[0], 0.f);
        o.y = fmaxf(acc[i][1] + bv[1], 0.f);
        o.z = fmaxf(acc[i][2] + bv[2], 0.f);
        o.w = fmaxf(acc[i][3] + bv[3], 0.f);
        *reinterpret_cast<float4*>(C + (size_t)m * N + n0 + tx * 4) = o;
    }
}

// ---------------------------------------------------------------------------
// mma.sync tf32 GEMM, 3-term fp32 emulation.
// C[M,N] = relu(A[M,K] @ W[N,K]^T + bias)
// CTA tile 128 x BN, BK = 32, 256 threads = 8 warps (4 x 2 grid),
// warp tile 32 x (BN/2). Requires M%128==0, N%BN==0, K%32==0.
// Smem: hi/lo planes, row stride 36 floats (conflict-free fragment reads).
// ---------------------------------------------------------------------------
template <int BN>
__global__ void __launch_bounds__(256) gemm_mma(
    const float* __restrict__ A, const float* __restrict__ W,
    const float* __restrict__ bias, float* __restrict__ C,
    int M, int N, int K)
{
    constexpr int NTW = BN / 16;             // n-tiles (of 8) per warp
    extern __shared__ float smf[];
    float* s_ah = smf;                       // 128*36
    float* s_al = smf + 128 * 36;
    float* s_wh = smf + 2 * 128 * 36;        // BN*36
    float* s_wl = s_wh + BN * 36;

    const int tid = threadIdx.x;
    const int wid = tid >> 5, lane = tid & 31;
    const int g = lane >> 2, tg = lane & 3;
    const int wm = (wid & 3) * 32;
    const int wn = (wid >> 2) * (BN / 2);
    const int m0 = blockIdx.x * 128;
    const int n0 = blockIdx.y * BN;

    float acc[2][NTW][4];
#pragma unroll
    for (int mt = 0; mt < 2; mt++)
#pragma unroll
        for (int nt = 0; nt < NTW; nt++)
#pragma unroll
            for (int j = 0; j < 4; j++) acc[mt][nt][j] = 0.f;

    for (int k0 = 0; k0 < K; k0 += 32) {
        // A tile 128x32 -> hi/lo
#pragma unroll
        for (int i = 0; i < 4; i++) {
            int idx = tid + i * 256;
            int r = idx >> 3, c4 = idx & 7;
            float4 v = *reinterpret_cast<const float4*>(
                A + (size_t)(m0 + r) * K + k0 + c4 * 4);
            float4 h, l;
            h.x = tf32r(v.x); l.x = tf32r(v.x - h.x);
            h.y = tf32r(v.y); l.y = tf32r(v.y - h.y);
            h.z = tf32r(v.z); l.z = tf32r(v.z - h.z);
            h.w = tf32r(v.w); l.w = tf32r(v.w - h.w);
            *reinterpret_cast<float4*>(s_ah + r * 36 + c4 * 4) = h;
            *reinterpret_cast<float4*>(s_al + r * 36 + c4 * 4) = l;
        }
        // W tile BNx32 -> hi/lo
#pragma unroll
        for (int i = 0; i < BN / 32; i++) {
            int idx = tid + i * 256;
            int r = idx >> 3, c4 = idx & 7;
            float4 v = *reinterpret_cast<const float4*>(
                W + (size_t)(n0 + r) * K + k0 + c4 * 4);
            float4 h, l;
            h.x = tf32r(v.x); l.x = tf32r(v.x - h.x);
            h.y = tf32r(v.y); l.y = tf32r(v.y - h.y);
            h.z = tf32r(v.z); l.z = tf32r(v.z - h.z);
            h.w = tf32r(v.w); l.w = tf32r(v.w - h.w);
            *reinterpret_cast<float4*>(s_wh + r * 36 + c4 * 4) = h;
            *reinterpret_cast<float4*>(s_wl + r * 36 + c4 * 4) = l;
        }
        __syncthreads();

#pragma unroll
        for (int kk = 0; kk < 4; kk++) {
            const int ck = kk * 8 + tg;
            uint32_t ah[2][4], al[2][4];
#pragma unroll
            for (int mt = 0; mt < 2; mt++) {
                int r0 = wm + mt * 16 + g;
                ah[mt][0] = __float_as_uint(s_ah[r0 * 36 + ck]);
                ah[mt][1] = __float_as_uint(s_ah[(r0 + 8) * 36 + ck]);
                ah[mt][2] = __float_as_uint(s_ah[r0 * 36 + ck + 4]);
                ah[mt][3] = __float_as_uint(s_ah[(r0 + 8) * 36 + ck + 4]);
                al[mt][0] = __float_as_uint(s_al[r0 * 36 + ck]);
                al[mt][1] = __float_as_uint(s_al[(r0 + 8) * 36 + ck]);
                al[mt][2] = __float_as_uint(s_al[r0 * 36 + ck + 4]);
                al[mt][3] = __float_as_uint(s_al[(r0 + 8) * 36 + ck + 4]);
            }
#pragma unroll
            for (int nt = 0; nt < NTW; nt++) {
                int n = wn + nt * 8 + g;
                uint32_t bh0 = __float_as_uint(s_wh[n * 36 + ck]);
                uint32_t bh1 = __float_as_uint(s_wh[n * 36 + ck + 4]);
                uint32_t bl0 = __float_as_uint(s_wl[n * 36 + ck]);
                uint32_t bl1 = __float_as_uint(s_wl[n * 36 + ck + 4]);
#pragma unroll
                for (int mt = 0; mt < 2; mt++) {
                    MMA_TF32(acc[mt][nt], ah[mt], bh0, bh1);
                    MMA_TF32(acc[mt][nt], ah[mt], bl0, bl1);
                    MMA_TF32(acc[mt][nt], al[mt], bh0, bh1);
                }
            }
        }
        __syncthreads();
    }

    // epilogue: bias + relu
#pragma unroll
    for (int mt = 0; mt < 2; mt++) {
#pragma unroll
        for (int nt = 0; nt < NTW; nt++) {
            int row = m0 + wm + mt * 16 + g;
            int col = n0 + wn + nt * 8 + 2 * tg;
            float b0 = __ldg(&bias[col]);
            float b1 = __ldg(&bias[col + 1]);
            float2 o0, o1;
            o0.x = fmaxf(acc[mt][nt][0] + b0, 0.f);
            o0.y = fmaxf(acc[mt][nt][1] + b1, 0.f);
            o1.x = fmaxf(acc[mt][nt][2] + b0, 0.f);
            o1.y = fmaxf(acc[mt][nt][3] + b1, 0.f);
            *reinterpret_cast<float2*>(C + (size_t)row * N + col) = o0;
            *reinterpret_cast<float2*>(C + (size_t)(row + 8) * N + col) = o1;
        }
    }
}

// ---------------------------------------------------------------------------
// Max-pools
// ---------------------------------------------------------------------------
__global__ void maxpool_k_kernel(const float* __restrict__ src,
                                 float* __restrict__ dst, int nc, int C)
{
    int t = blockIdx.x * blockDim.x + threadIdx.x;
    if (t >= nc * C) return;
    int o = t % C, c = t / C;
    const float* p = src + (size_t)c * NS * C + o;
    float m = p[0];
#pragma unroll 4
    for (int k = 1; k < NS; k++) m = fmaxf(m, p[(size_t)k * C]);
    dst[t] = m;
}

__global__ void finalpool_kernel(const float* __restrict__ src,
                                 float* __restrict__ out)
{
    int t = blockIdx.x * blockDim.x + threadIdx.x;
    if (t >= BB * 1024) return;
    int b = t >> 10, o = t & 1023;
    const float* p = src + (size_t)b * S2 * 1024 + o;
    float m = p[0];
    for (int k = 1; k < S2; k++) m = fmaxf(m, p[(size_t)k * 1024]);
    out[t] = m;
}

// ---------------------------------------------------------------------------
static void run_mma(const float* A, const float* W, const float* bias,
                    float* C, int M, int N, int K)
{
    if (N % 128 == 0) {
        const int smem = (2 * 128 + 2 * 128) * 36 * 4;   // 73728
        cudaFuncSetAttribute(gemm_mma<128>,
                             cudaFuncAttributeMaxDynamicSharedMemorySize, smem);
        dim3 g(M / 128, N / 128);
        gemm_mma<128><<<g, 256, smem>>>(A, W, bias, C, M, N, K);
    } else {
        const int smem = (2 * 128 + 2 * 64) * 36 * 4;    // 55296
        cudaFuncSetAttribute(gemm_mma<64>,
                             cudaFuncAttributeMaxDynamicSharedMemorySize, smem);
        dim3 g(M / 128, N / 64);
        gemm_mma<64><<<g, 256, smem>>>(A, W, bias, C, M, N, K);
    }
}

extern "C" void kernel_launch(void* const* d_in, const int* in_sizes, int n_in,
                              void* d_out, int out_size)
{
    (void)in_sizes; (void)n_in; (void)out_size;
    const float* data = (const float*)d_in[0];
    const float *w[9], *bi[9];
    for (int i = 0; i < 9; i++) {
        w[i]  = (const float*)d_in[1 + 2 * i];
        bi[i] = (const float*)d_in[2 + 2 * i];
    }

    float *scr0, *scr1, *f1, *f2, *nx1, *nx2, *x3, *w2p, *w3p;
    int *g1, *g2;
    cudaGetSymbolAddress((void**)&scr0, g_scr0);
    cudaGetSymbolAddress((void**)&scr1, g_scr1);
    cudaGetSymbolAddress((void**)&f1, g_f1);
    cudaGetSymbolAddress((void**)&f2, g_f2);
    cudaGetSymbolAddress((void**)&nx1, g_nx1);
    cudaGetSymbolAddress((void**)&nx2, g_nx2);
    cudaGetSymbolAddress((void**)&g1, g_g1);
    cudaGetSymbolAddress((void**)&g2, g_g2);
    cudaGetSymbolAddress((void**)&x3, g_x3);
    cudaGetSymbolAddress((void**)&w2p, g_w2p);
    cudaGetSymbolAddress((void**)&w3p, g_w3p);

    const float R2a = (float)(0.2 * 0.2);
    const float R2b = (float)(0.4 * 0.4);

    // weight pads (independent; launch early)
    padw_kernel<<<(128 * 160 + 255) / 256, 256>>>(w[3], w2p, 128, 131, 160);
    padw_kernel<<<(256 * 288 + 255) / 256, 256>>>(w[6], w3p, 256, 259, 288);

    // ---- Stage 1 ----
    fps_kernel<N1, S1, 512><<<BB, 512>>>(data, nx1);
    ballq_kernel<N1><<<(BB * S1) / 8, 256>>>(data, nx1, S1, R2a, g1);
    gather1_kernel<<<(BB * S1 * NS + 255) / 256, 256>>>(data, scr1);
    {
        dim3 g((BB * S1 * NS) / 128, 1);
        gemm_bias_relu<<<g, 256>>>(scr1, w[0], bi[0], scr0, BB * S1 * NS, 64, 3, 3);
    }
    run_mma(scr0, w[1], bi[1], scr1, BB * S1 * NS, 64, 64);
    run_mma(scr1, w[2], bi[2], scr0, BB * S1 * NS, 128, 64);
    maxpool_k_kernel<<<(BB * S1 * 128 + 255) / 256, 256>>>(scr0, f1, BB * S1, 128);

    // ---- Stage 2 ----
    fps_kernel<S1, S2, 256><<<BB, 256>>>(nx1, nx2);
    ballq_kernel<S1><<<(BB * S2) / 8, 256>>>(nx1, nx2, S2, R2b, g2);
    gather2_kernel<<<(BB * S2 * NS) / 4, 128>>>(scr0);   // 131072 x 160 (padded)
    run_mma(scr0, w2p, bi[3], scr1, BB * S2 * NS, 128, 160);
    run_mma(scr1, w[4], bi[4], scr0, BB * S2 * NS, 128, 128);
    run_mma(scr0, w[5], bi[5], scr1, BB * S2 * NS, 256, 128);
    maxpool_k_kernel<<<(BB * S2 * 256 + 255) / 256, 256>>>(scr1, f2, BB * S2, 256);

    // ---- Stage 3 (group-all) ----
    concat3_kernel<<<(BB * S2 * 288 + 255) / 256, 256>>>(x3);  // 4096 x 288 (padded)
    run_mma(x3, w3p, bi[6], scr0, BB * S2, 256, 288);
    run_mma(scr0, w[7], bi[7], scr1, BB * S2, 512, 256);
    run_mma(scr1, w[8], bi[8], scr0, BB * S2, 1024, 512);
    finalpool_kernel<<<(BB * 1024 + 255) / 256, 256>>>(scr0, (float*)d_out);
}

// round 8
// speedup vs baseline: 1.5627x; 1.1202x over previous
#include <cuda_runtime.h>
#include <cstdint>

// ---------------------------------------------------------------------------
// PointNet++ encoder on GB300 (base sm_103 PTX: mma.sync + cp.async only).
// FPS / ball-query / gathers: exact fp32 (bitwise-match indices vs JAX ref).
// MLP layers K>=32: mma.sync m16n8k8 tf32, 3-term fp32 emulation, raw-fp32
// smem with register-side hi/lo split, cp.async double buffering.
// ---------------------------------------------------------------------------

#define BB   32
#define N1   4096
#define S1   256
#define S2   128
#define NS   32

__device__ float g_scr0[262144 * 128];   // 134 MB
__device__ float g_scr1[262144 * 128];   // 134 MB
__device__ float g_f1[BB * S1 * 128];
__device__ float g_f2[BB * S2 * 256];
__device__ float g_nx1[BB * S1 * 3];
__device__ float g_nx2[BB * S2 * 3];
__device__ int   g_g1[BB * S1 * NS];
__device__ int   g_g2[BB * S2 * NS];
__device__ float g_x3[BB * S2 * 288];
__device__ float g_w2p[128 * 160];
__device__ float g_w3p[256 * 288];

__device__ __forceinline__ float tf32r(float x) {
    float r;
    asm("cvt.rna.tf32.f32 %0, %1;" : "=f"(r) : "f"(x));
    return r;
}
__device__ __forceinline__ uint32_t smem_u32(const void* p) {
    uint32_t a;
    asm("{ .reg .u64 t; cvta.to.shared.u64 t, %1; cvt.u32.u64 %0, t; }"
        : "=r"(a) : "l"(p));
    return a;
}
__device__ __forceinline__ void cp16(uint32_t dst, const void* src) {
    asm volatile("cp.async.ca.shared.global [%0], [%1], 16;"
                 :: "r"(dst), "l"(src) : "memory");
}
#define CP_COMMIT() asm volatile("cp.async.commit_group;" ::: "memory")
#define CP_WAIT1()  asm volatile("cp.async.wait_group 1;" ::: "memory")

#define MMA_TF32(c, a, b0, b1)                                                \
    asm volatile(                                                             \
        "mma.sync.aligned.m16n8k8.row.col.f32.tf32.tf32.f32 "                 \
        "{%0,%1,%2,%3}, {%4,%5,%6,%7}, {%8,%9}, {%0,%1,%2,%3};"               \
        : "+f"((c)[0]), "+f"((c)[1]), "+f"((c)[2]), "+f"((c)[3])              \
        : "r"((a)[0]), "r"((a)[1]), "r"((a)[2]), "r"((a)[3]),                 \
          "r"(b0), "r"(b1))

// ---------------------------------------------------------------------------
// FPS (bitwise exact vs reference)
// ---------------------------------------------------------------------------
template <int N, int NPTS, int THREADS>
__global__ void __launch_bounds__(THREADS) fps_kernel(
    const float* __restrict__ xyz_all, float* __restrict__ new_xyz)
{
    constexpr int PPT = N / THREADS;
    const int b = blockIdx.x;
    const int t = threadIdx.x;
    const float* xyz = xyz_all + (size_t)b * N * 3;

    float px[PPT], py[PPT], pz[PPT], md[PPT];
#pragma unroll
    for (int j = 0; j < PPT; j++) {
        int i = t + j * THREADS;
        px[j] = xyz[i * 3 + 0];
        py[j] = xyz[i * 3 + 1];
        pz[j] = xyz[i * 3 + 2];
        md[j] = 1e10f;
    }

    __shared__ unsigned long long wred[THREADS / 32];
    __shared__ int s_last;

    int last = 0;
    for (int it = 0; it < NPTS; it++) {
        float lx = __ldg(&xyz[last * 3 + 0]);
        float ly = __ldg(&xyz[last * 3 + 1]);
        float lz = __ldg(&xyz[last * 3 + 2]);
        if (t == 0) {
            float* o = new_xyz + (size_t)(b * NPTS + it) * 3;
            o[0] = lx; o[1] = ly; o[2] = lz;
        }
        unsigned long long best = 0ull;
#pragma unroll
        for (int j = 0; j < PPT; j++) {
            float dx = px[j] - lx, dy = py[j] - ly, dz = pz[j] - lz;
            float d = __fadd_rn(__fadd_rn(__fmul_rn(dx, dx), __fmul_rn(dy, dy)),
                                __fmul_rn(dz, dz));
            float m = fminf(md[j], d);
            md[j] = m;
            unsigned long long key =
                (((unsigned long long)__float_as_uint(m)) << 32) |
                (unsigned)(0xFFFFFFFFu - (unsigned)(t + j * THREADS));
            best = (key > best) ? key : best;
        }
#pragma unroll
        for (int off = 16; off > 0; off >>= 1) {
            unsigned long long o = __shfl_down_sync(0xffffffffu, best, off);
            best = (o > best) ? o : best;
        }
        if ((t & 31) == 0) wred[t >> 5] = best;
        __syncthreads();
        if (t < 32) {
            unsigned long long v = (t < THREADS / 32) ? wred[t] : 0ull;
#pragma unroll
            for (int off = 16; off > 0; off >>= 1) {
                unsigned long long o = __shfl_down_sync(0xffffffffu, v, off);
                v = (o > v) ? o : v;
            }
            if (t == 0)
                s_last = (int)(0xFFFFFFFFu - (unsigned)(v & 0xFFFFFFFFull));
        }
        __syncthreads();
        last = s_last;
    }
}

// ---------------------------------------------------------------------------
// Stage-1 ball query: point cloud staged in smem, 8 blocks/batch,
// 8 warps x 4 centers per block. Identical arithmetic/order -> exact indices.
// ---------------------------------------------------------------------------
__global__ void __launch_bounds__(256) ballq1_smem(
    const float* __restrict__ xyz_all, const float* __restrict__ centers,
    float R2, int* __restrict__ out)
{
    extern __shared__ float sm[];
    float* sx = sm;
    float* sy = sm + N1;
    float* sz = sm + 2 * N1;
    int* buf = (int*)(sm + 3 * N1);          // [8][32]

    const int b = blockIdx.x >> 3;
    const int grp = blockIdx.x & 7;
    const float* xyz = xyz_all + (size_t)b * N1 * 3;
    for (int i = threadIdx.x; i < N1; i += 256) {
        sx[i] = xyz[i * 3 + 0];
        sy[i] = xyz[i * 3 + 1];
        sz[i] = xyz[i * 3 + 2];
    }
    __syncthreads();

    const int wid = threadIdx.x >> 5, lane = threadIdx.x & 31;
    int* mybuf = buf + wid * 32;
#pragma unroll
    for (int ci = 0; ci < 4; ci++) {
        const int s = grp * 32 + wid * 4 + ci;       // center within batch
        const int gw = b * S1 + s;
        const float cx = centers[gw * 3 + 0];
        const float cy = centers[gw * 3 + 1];
        const float cz = centers[gw * 3 + 2];
        int cnt = 0;
        for (int base = 0; base < N1; base += 32) {
            int p = base + lane;
            float dx = sx[p] - cx;
            float dy = sy[p] - cy;
            float dz = sz[p] - cz;
            float d2 = __fadd_rn(__fadd_rn(__fmul_rn(dx, dx), __fmul_rn(dy, dy)),
                                 __fmul_rn(dz, dz));
            bool pred = d2 < R2;
            unsigned mask = __ballot_sync(0xffffffffu, pred);
            if (pred) {
                int pos = cnt + __popc(mask & ((1u << lane) - 1u));
                if (pos < NS) mybuf[pos] = p;
            }
            cnt += __popc(mask);
            if (cnt >= NS) break;
        }
        __syncwarp();
        int nv = cnt < NS ? cnt : NS;
        int first = (cnt > 0) ? mybuf[0] : 0;
        int val = (lane < nv) ? mybuf[lane] : first;
        out[(size_t)gw * NS + lane] = val;
        __syncwarp();
    }
}

// ---------------------------------------------------------------------------
// Stage-2 ball query (N=256, cheap): global version, exact
// ---------------------------------------------------------------------------
template <int N>
__global__ void __launch_bounds__(256) ballq_kernel(
    const float* __restrict__ xyz_all, const float* __restrict__ centers,
    int S, float R2, int* __restrict__ out)
{
    const int gw = (blockIdx.x * blockDim.x + threadIdx.x) >> 5;
    const int lane = threadIdx.x & 31;
    const int wl = threadIdx.x >> 5;
    __shared__ int buf[8][32];

    const int b = gw / S;
    const float* xyz = xyz_all + (size_t)b * N * 3;
    const float cx = centers[gw * 3 + 0];
    const float cy = centers[gw * 3 + 1];
    const float cz = centers[gw * 3 + 2];

    int cnt = 0;
    for (int base = 0; base < N; base += 32) {
        int p = base + lane;
        float dx = xyz[p * 3 + 0] - cx;
        float dy = xyz[p * 3 + 1] - cy;
        float dz = xyz[p * 3 + 2] - cz;
        float d2 = __fadd_rn(__fadd_rn(__fmul_rn(dx, dx), __fmul_rn(dy, dy)),
                             __fmul_rn(dz, dz));
        bool pred = d2 < R2;
        unsigned mask = __ballot_sync(0xffffffffu, pred);
        if (pred) {
            int pos = cnt + __popc(mask & ((1u << lane) - 1u));
            if (pos < NS) buf[wl][pos] = p;
        }
        cnt += __popc(mask);
        if (cnt >= NS) break;
    }
    __syncwarp();
    int nv = cnt < NS ? cnt : NS;
    int first = (cnt > 0) ? buf[wl][0] : 0;
    int val = (lane < nv) ? buf[wl][lane] : first;
    out[(size_t)gw * NS + lane] = val;
}

// ---------------------------------------------------------------------------
// Gathers / concat / weight pads
// ---------------------------------------------------------------------------
__global__ void gather1_kernel(const float* __restrict__ data,
                               float* __restrict__ x1)
{
    int r = blockIdx.x * blockDim.x + threadIdx.x;
    if (r >= BB * S1 * NS) return;
    int c = r >> 5;
    int b = c >> 8;
    int g = g_g1[r];
    const float* p = data + ((size_t)b * N1 + g) * 3;
    const float* ctr = g_nx1 + (size_t)c * 3;
    float* o = x1 + (size_t)r * 3;
    o[0] = p[0] - ctr[0];
    o[1] = p[1] - ctr[1];
    o[2] = p[2] - ctr[2];
}

__global__ void gather2_kernel(float* __restrict__ x2)
{
    int r = blockIdx.x * 4 + (threadIdx.x >> 5);
    int lane = threadIdx.x & 31;
    int c = r >> 5;
    int b = c >> 7;
    int j = g_g2[r];
    const float* src = g_nx1 + ((size_t)b * S1 + j) * 3;
    const float* ctr = g_nx2 + (size_t)c * 3;
    const float* f = g_f1 + ((size_t)b * S1 + j) * 128;
    float* dst = x2 + (size_t)r * 160;
    for (int col = lane; col < 160; col += 32)
        dst[col] = (col < 3) ? (src[col] - ctr[col])
                             : (col < 131 ? f[col - 3] : 0.f);
}

__global__ void concat3_kernel(float* __restrict__ x3)
{
    int t = blockIdx.x * blockDim.x + threadIdx.x;
    if (t >= BB * S2 * 288) return;
    int r = t / 288, col = t - r * 288;
    x3[t] = (col < 3) ? g_nx2[(size_t)r * 3 + col]
                      : (col < 259 ? g_f2[(size_t)r * 256 + (col - 3)] : 0.f);
}

__global__ void padw_kernel(const float* __restrict__ w, float* __restrict__ o,
                            int n, int kin, int kout)
{
    int t = blockIdx.x * blockDim.x + threadIdx.x;
    if (t >= n * kout) return;
    int r = t / kout, c = t - r * kout;
    o[t] = (c < kin) ? w[r * kin + c] : 0.f;
}

// ---------------------------------------------------------------------------
// SGEMM for layer 1_0 (K=3, memory-bound)
// ---------------------------------------------------------------------------
__global__ void __launch_bounds__(256) gemm_bias_relu(
    const float* __restrict__ A, const float* __restrict__ W,
    const float* __restrict__ bias, float* __restrict__ C,
    int M, int N, int K, int lda)
{
    __shared__ float As[16][128];
    __shared__ float Ws[16][64];
    const int tid = threadIdx.x;
    const int ty = tid >> 4, tx = tid & 15;
    const int m0 = blockIdx.x * 128;
    const int n0 = blockIdx.y * 64;

    const int a_m = tid >> 1;
    const int a_k0 = (tid & 1) * 8;
    const int w_n = tid >> 2;
    const int w_k0 = (tid & 3) * 4;

    const float* Arow = A + (size_t)(m0 + a_m) * lda;
    const float* Wrow = W + (size_t)(n0 + w_n) * K;

    float acc[8][4];
#pragma unroll
    for (int i = 0; i < 8; i++)
#pragma unroll
        for (int j = 0; j < 4; j++) acc[i][j] = 0.f;

    for (int k0 = 0; k0 < K; k0 += 16) {
#pragma unroll
        for (int i = 0; i < 8; i++) {
            int k = k0 + a_k0 + i;
            As[a_k0 + i][a_m] = (k < K) ? Arow[k] : 0.f;
        }
#pragma unroll
        for (int i = 0; i < 4; i++) {
            int k = k0 + w_k0 + i;
            Ws[w_k0 + i][w_n] = (k < K) ? Wrow[k] : 0.f;
        }
        __syncthreads();
#pragma unroll
        for (int kk = 0; kk < 16; kk++) {
            float a[8], wv[4];
#pragma unroll
            for (int i = 0; i < 8; i++) a[i] = As[kk][ty * 8 + i];
#pragma unroll
            for (int j = 0; j < 4; j++) wv[j] = Ws[kk][tx * 4 + j];
#pragma unroll
            for (int i = 0; i < 8; i++)
#pragma unroll
                for (int j = 0; j < 4; j++)
                    acc[i][j] = fmaf(a[i], wv[j], acc[i][j]);
        }
        __syncthreads();
    }

    float bv[4];
#pragma unroll
    for (int j = 0; j < 4; j++) bv[j] = bias[n0 + tx * 4 + j];
#pragma unroll
    for (int i = 0; i < 8; i++) {
        int m = m0 + ty * 8 + i;
        float4 o;
        o.x = fmaxf(acc[i][0] + bv[0], 0.f);
        o.y = fmaxf(acc[i][1] + bv[1], 0.f);
        o.z = fmaxf(acc[i][2] + bv[2], 0.f);
        o.w = fmaxf(acc[i][3] + bv[3], 0.f);
        *reinterpret_cast<float4*>(C + (size_t)m * N + n0 + tx * 4) = o;
    }
}

// ---------------------------------------------------------------------------
// mma.sync tf32 GEMM v2: raw-fp32 smem + register hi/lo split + cp.async
// double buffering. CTA tile 128 x BN, BK=32, 256 threads (8 warps, 4x2),
// warp tile 32 x (BN/2). M%128==0, N%BN==0, K%32==0.
// Smem row stride 36 floats (conflict-free fragment reads).
// ---------------------------------------------------------------------------
template <int BN>
__global__ void __launch_bounds__(256) gemm_mma(
    const float* __restrict__ A, const float* __restrict__ W,
    const float* __restrict__ bias, float* __restrict__ C,
    int M, int N, int K)
{
    constexpr int NTW = BN / 16;
    constexpr int SLOT = (128 + BN) * 36;          // floats per slot
    extern __shared__ float smf[];

    const int tid = threadIdx.x;
    const int wid = tid >> 5, lane = tid & 31;
    const int g = lane >> 2, tg = lane & 3;
    const int wm = (wid & 3) * 32;
    const int wn = (wid >> 2) * (BN / 2);
    const int m0 = blockIdx.x * 128;
    const int n0 = blockIdx.y * BN;
    const uint32_t smbase = smem_u32(smf);

    float acc[2][NTW][4];
#pragma unroll
    for (int mt = 0; mt < 2; mt++)
#pragma unroll
        for (int nt = 0; nt < NTW; nt++)
#pragma unroll
            for (int j = 0; j < 4; j++) acc[mt][nt][j] = 0.f;

    const int KC = K >> 5;

    // async copy of one 32-col chunk into slot s
    auto prefetch = [&](int kc, int s) {
        const uint32_t sb = smbase + (uint32_t)(s * SLOT) * 4u;
        // A: 128 rows x 8 segs of 16B
#pragma unroll
        for (int i = 0; i < 4; i++) {
            int seg = tid + i * 256;
            int r = seg >> 3, c16 = seg & 7;
            cp16(sb + (uint32_t)(r * 36 + c16 * 4) * 4u,
                 A + (size_t)(m0 + r) * K + kc * 32 + c16 * 4);
        }
        // W: BN rows x 8 segs
#pragma unroll
        for (int i = 0; i < BN / 32; i++) {
            int seg = tid + i * 256;
            int r = seg >> 3, c16 = seg & 7;
            cp16(sb + (uint32_t)((128 + r) * 36 + c16 * 4) * 4u,
                 W + (size_t)(n0 + r) * K + kc * 32 + c16 * 4);
        }
    };

    prefetch(0, 0);
    CP_COMMIT();

    for (int kc = 0; kc < KC; kc++) {
        if (kc + 1 < KC) prefetch(kc + 1, (kc + 1) & 1);
        CP_COMMIT();
        CP_WAIT1();
        __syncthreads();

        const float* s_a = smf + (kc & 1) * SLOT;
        const float* s_w = s_a + 128 * 36;

#pragma unroll
        for (int kk = 0; kk < 4; kk++) {
            const int ck = kk * 8 + tg;
            uint32_t ah[2][4], al[2][4];
#pragma unroll
            for (int mt = 0; mt < 2; mt++) {
                int r0 = wm + mt * 16 + g;
                float a0 = s_a[r0 * 36 + ck];
                float a1 = s_a[(r0 + 8) * 36 + ck];
                float a2 = s_a[r0 * 36 + ck + 4];
                float a3 = s_a[(r0 + 8) * 36 + ck + 4];
                float h0 = tf32r(a0), h1 = tf32r(a1);
                float h2 = tf32r(a2), h3 = tf32r(a3);
                ah[mt][0] = __float_as_uint(h0);
                ah[mt][1] = __float_as_uint(h1);
                ah[mt][2] = __float_as_uint(h2);
                ah[mt][3] = __float_as_uint(h3);
                al[mt][0] = __float_as_uint(tf32r(a0 - h0));
                al[mt][1] = __float_as_uint(tf32r(a1 - h1));
                al[mt][2] = __float_as_uint(tf32r(a2 - h2));
                al[mt][3] = __float_as_uint(tf32r(a3 - h3));
            }
#pragma unroll
            for (int nt = 0; nt < NTW; nt++) {
                int n = wn + nt * 8 + g;
                float b0 = s_w[n * 36 + ck];
                float b1 = s_w[n * 36 + ck + 4];
                float hb0 = tf32r(b0), hb1 = tf32r(b1);
                uint32_t bh0 = __float_as_uint(hb0);
                uint32_t bh1 = __float_as_uint(hb1);
                uint32_t bl0 = __float_as_uint(tf32r(b0 - hb0));
                uint32_t bl1 = __float_as_uint(tf32r(b1 - hb1));
#pragma unroll
                for (int mt = 0; mt < 2; mt++) {
                    MMA_TF32(acc[mt][nt], ah[mt], bh0, bh1);
                    MMA_TF32(acc[mt][nt], ah[mt], bl0, bl1);
                    MMA_TF32(acc[mt][nt], al[mt], bh0, bh1);
                }
            }
        }
        __syncthreads();
    }

    // epilogue: bias + relu
#pragma unroll
    for (int mt = 0; mt < 2; mt++) {
#pragma unroll
        for (int nt = 0; nt < NTW; nt++) {
            int row = m0 + wm + mt * 16 + g;
            int col = n0 + wn + nt * 8 + 2 * tg;
            float b0 = __ldg(&bias[col]);
            float b1 = __ldg(&bias[col + 1]);
            float2 o0, o1;
            o0.x = fmaxf(acc[mt][nt][0] + b0, 0.f);
            o0.y = fmaxf(acc[mt][nt][1] + b1, 0.f);
            o1.x = fmaxf(acc[mt][nt][2] + b0, 0.f);
            o1.y = fmaxf(acc[mt][nt][3] + b1, 0.f);
            *reinterpret_cast<float2*>(C + (size_t)row * N + col) = o0;
            *reinterpret_cast<float2*>(C + (size_t)(row + 8) * N + col) = o1;
        }
    }
}

// ---------------------------------------------------------------------------
// Max-pools
// ---------------------------------------------------------------------------
__global__ void maxpool_k_kernel(const float* __restrict__ src,
                                 float* __restrict__ dst, int nc, int C)
{
    int t = blockIdx.x * blockDim.x + threadIdx.x;
    if (t >= nc * C) return;
    int o = t % C, c = t / C;
    const float* p = src + (size_t)c * NS * C + o;
    float m = p[0];
#pragma unroll 4
    for (int k = 1; k < NS; k++) m = fmaxf(m, p[(size_t)k * C]);
    dst[t] = m;
}

__global__ void finalpool_kernel(const float* __restrict__ src,
                                 float* __restrict__ out)
{
    int t = blockIdx.x * blockDim.x + threadIdx.x;
    if (t >= BB * 1024) return;
    int b = t >> 10, o = t & 1023;
    const float* p = src + (size_t)b * S2 * 1024 + o;
    float m = p[0];
    for (int k = 1; k < S2; k++) m = fmaxf(m, p[(size_t)k * 1024]);
    out[t] = m;
}

// ---------------------------------------------------------------------------
static void run_mma(const float* A, const float* W, const float* bias,
                    float* C, int M, int N, int K)
{
    if (N % 128 == 0) {
        const int smem = 2 * (128 + 128) * 36 * 4;   // 73728
        cudaFuncSetAttribute(gemm_mma<128>,
                             cudaFuncAttributeMaxDynamicSharedMemorySize, smem);
        dim3 g(M / 128, N / 128);
        gemm_mma<128><<<g, 256, smem>>>(A, W, bias, C, M, N, K);
    } else {
        const int smem = 2 * (128 + 64) * 36 * 4;    // 55296
        cudaFuncSetAttribute(gemm_mma<64>,
                             cudaFuncAttributeMaxDynamicSharedMemorySize, smem);
        dim3 g(M / 128, N / 64);
        gemm_mma<64><<<g, 256, smem>>>(A, W, bias, C, M, N, K);
    }
}

extern "C" void kernel_launch(void* const* d_in, const int* in_sizes, int n_in,
                              void* d_out, int out_size)
{
    (void)in_sizes; (void)n_in; (void)out_size;
    const float* data = (const float*)d_in[0];
    const float *w[9], *bi[9];
    for (int i = 0; i < 9; i++) {
        w[i]  = (const float*)d_in[1 + 2 * i];
        bi[i] = (const float*)d_in[2 + 2 * i];
    }

    float *scr0, *scr1, *f1, *f2, *nx1, *nx2, *x3, *w2p, *w3p;
    int *g1, *g2;
    cudaGetSymbolAddress((void**)&scr0, g_scr0);
    cudaGetSymbolAddress((void**)&scr1, g_scr1);
    cudaGetSymbolAddress((void**)&f1, g_f1);
    cudaGetSymbolAddress((void**)&f2, g_f2);
    cudaGetSymbolAddress((void**)&nx1, g_nx1);
    cudaGetSymbolAddress((void**)&nx2, g_nx2);
    cudaGetSymbolAddress((void**)&g1, g_g1);
    cudaGetSymbolAddress((void**)&g2, g_g2);
    cudaGetSymbolAddress((void**)&x3, g_x3);
    cudaGetSymbolAddress((void**)&w2p, g_w2p);
    cudaGetSymbolAddress((void**)&w3p, g_w3p);

    const float R2a = (float)(0.2 * 0.2);
    const float R2b = (float)(0.4 * 0.4);

    padw_kernel<<<(128 * 160 + 255) / 256, 256>>>(w[3], w2p, 128, 131, 160);
    padw_kernel<<<(256 * 288 + 255) / 256, 256>>>(w[6], w3p, 256, 259, 288);

    // ---- Stage 1 ----
    fps_kernel<N1, S1, 512><<<BB, 512>>>(data, nx1);
    {
        const int smem = 3 * N1 * 4 + 8 * 32 * 4;   // 50176
        cudaFuncSetAttribute(ballq1_smem,
                             cudaFuncAttributeMaxDynamicSharedMemorySize, smem);
        ballq1_smem<<<BB * 8, 256, smem>>>(data, nx1, R2a, g1);
    }
    gather1_kernel<<<(BB * S1 * NS + 255) / 256, 256>>>(data, scr1);
    {
        dim3 g((BB * S1 * NS) / 128, 1);
        gemm_bias_relu<<<g, 256>>>(scr1, w[0], bi[0], scr0, BB * S1 * NS, 64, 3, 3);
    }
    run_mma(scr0, w[1], bi[1], scr1, BB * S1 * NS, 64, 64);
    run_mma(scr1, w[2], bi[2], scr0, BB * S1 * NS, 128, 64);
    maxpool_k_kernel<<<(BB * S1 * 128 + 255) / 256, 256>>>(scr0, f1, BB * S1, 128);

    // ---- Stage 2 ----
    fps_kernel<S1, S2, 256><<<BB, 256>>>(nx1, nx2);
    ballq_kernel<S1><<<(BB * S2) / 8, 256>>>(nx1, nx2, S2, R2b, g2);
    gather2_kernel<<<(BB * S2 * NS) / 4, 128>>>(scr0);
    run_mma(scr0, w2p, bi[3], scr1, BB * S2 * NS, 128, 160);
    run_mma(scr1, w[4], bi[4], scr0, BB * S2 * NS, 128, 128);
    run_mma(scr0, w[5], bi[5], scr1, BB * S2 * NS, 256, 128);
    maxpool_k_kernel<<<(BB * S2 * 256 + 255) / 256, 256>>>(scr1, f2, BB * S2, 256);

    // ---- Stage 3 ----
    concat3_kernel<<<(BB * S2 * 288 + 255) / 256, 256>>>(x3);
    run_mma(x3, w3p, bi[6], scr0, BB * S2, 256, 288);
    run_mma(scr0, w[7], bi[7], scr1, BB * S2, 512, 256);
    run_mma(scr1, w[8], bi[8], scr0, BB * S2, 1024, 512);
    finalpool_kernel<<<(BB * 1024 + 255) / 256, 256>>>(scr0, (float*)d_out);
}

// round 9
// speedup vs baseline: 1.7490x; 1.1192x over previous
#include <cuda_runtime.h>
#include <cstdint>

// ---------------------------------------------------------------------------
// PointNet++ encoder on GB300 (base sm_103 PTX: mma.sync + cp.async only).
// FPS / ball-query / gathers: exact fp32 (bitwise-match indices vs JAX ref).
// MLP layers K>=32: mma.sync m16n8k8 tf32, 3-term fp32 emulation, raw-fp32
// smem with register-side hi/lo split, cp.async double buffering.
// Max-pool layers (1_2, 2_2, 3_2): pool fused into GEMM epilogue.
// ---------------------------------------------------------------------------

#define BB   32
#define N1   4096
#define S1   256
#define S2   128
#define NS   32

__device__ float g_scr0[262144 * 128];   // 134 MB
__device__ float g_scr1[262144 * 128];   // 134 MB
__device__ float g_f1[BB * S1 * 128];
__device__ float g_f2[BB * S2 * 256];
__device__ float g_nx1[BB * S1 * 3];
__device__ float g_nx2[BB * S2 * 3];
__device__ int   g_g1[BB * S1 * NS];
__device__ int   g_g2[BB * S2 * NS];
__device__ float g_x3[BB * S2 * 288];
__device__ float g_w2p[128 * 160];
__device__ float g_w3p[256 * 288];

__device__ __forceinline__ float tf32r(float x) {
    float r;
    asm("cvt.rna.tf32.f32 %0, %1;" : "=f"(r) : "f"(x));
    return r;
}
__device__ __forceinline__ uint32_t smem_u32(const void* p) {
    uint32_t a;
    asm("{ .reg .u64 t; cvta.to.shared.u64 t, %1; cvt.u32.u64 %0, t; }"
        : "=r"(a) : "l"(p));
    return a;
}
__device__ __forceinline__ void cp16(uint32_t dst, const void* src) {
    asm volatile("cp.async.ca.shared.global [%0], [%1], 16;"
                 :: "r"(dst), "l"(src) : "memory");
}
#define CP_COMMIT() asm volatile("cp.async.commit_group;" ::: "memory")
#define CP_WAIT1()  asm volatile("cp.async.wait_group 1;" ::: "memory")

#define MMA_TF32(c, a, b0, b1)                                                \
    asm volatile(                                                             \
        "mma.sync.aligned.m16n8k8.row.col.f32.tf32.tf32.f32 "                 \
        "{%0,%1,%2,%3}, {%4,%5,%6,%7}, {%8,%9}, {%0,%1,%2,%3};"               \
        : "+f"((c)[0]), "+f"((c)[1]), "+f"((c)[2]), "+f"((c)[3])              \
        : "r"((a)[0]), "r"((a)[1]), "r"((a)[2]), "r"((a)[3]),                 \
          "r"(b0), "r"(b1))

// ---------------------------------------------------------------------------
// FPS (bitwise exact vs reference)
// ---------------------------------------------------------------------------
template <int N, int NPTS, int THREADS>
__global__ void __launch_bounds__(THREADS) fps_kernel(
    const float* __restrict__ xyz_all, float* __restrict__ new_xyz)
{
    constexpr int PPT = N / THREADS;
    const int b = blockIdx.x;
    const int t = threadIdx.x;
    const float* xyz = xyz_all + (size_t)b * N * 3;

    float px[PPT], py[PPT], pz[PPT], md[PPT];
#pragma unroll
    for (int j = 0; j < PPT; j++) {
        int i = t + j * THREADS;
        px[j] = xyz[i * 3 + 0];
        py[j] = xyz[i * 3 + 1];
        pz[j] = xyz[i * 3 + 2];
        md[j] = 1e10f;
    }

    __shared__ unsigned long long wred[THREADS / 32];
    __shared__ int s_last;

    int last = 0;
    for (int it = 0; it < NPTS; it++) {
        float lx = __ldg(&xyz[last * 3 + 0]);
        float ly = __ldg(&xyz[last * 3 + 1]);
        float lz = __ldg(&xyz[last * 3 + 2]);
        if (t == 0) {
            float* o = new_xyz + (size_t)(b * NPTS + it) * 3;
            o[0] = lx; o[1] = ly; o[2] = lz;
        }
        unsigned long long best = 0ull;
#pragma unroll
        for (int j = 0; j < PPT; j++) {
            float dx = px[j] - lx, dy = py[j] - ly, dz = pz[j] - lz;
            float d = __fadd_rn(__fadd_rn(__fmul_rn(dx, dx), __fmul_rn(dy, dy)),
                                __fmul_rn(dz, dz));
            float m = fminf(md[j], d);
            md[j] = m;
            unsigned long long key =
                (((unsigned long long)__float_as_uint(m)) << 32) |
                (unsigned)(0xFFFFFFFFu - (unsigned)(t + j * THREADS));
            best = (key > best) ? key : best;
        }
#pragma unroll
        for (int off = 16; off > 0; off >>= 1) {
            unsigned long long o = __shfl_down_sync(0xffffffffu, best, off);
            best = (o > best) ? o : best;
        }
        if ((t & 31) == 0) wred[t >> 5] = best;
        __syncthreads();
        if (t < 32) {
            unsigned long long v = (t < THREADS / 32) ? wred[t] : 0ull;
#pragma unroll
            for (int off = 16; off > 0; off >>= 1) {
                unsigned long long o = __shfl_down_sync(0xffffffffu, v, off);
                v = (o > v) ? o : v;
            }
            if (t == 0)
                s_last = (int)(0xFFFFFFFFu - (unsigned)(v & 0xFFFFFFFFull));
        }
        __syncthreads();
        last = s_last;
    }
}

// ---------------------------------------------------------------------------
// Stage-1 ball query: 32 blocks/batch, one warp per center, smem-staged cloud.
// Identical per-center arithmetic/order -> exact indices.
// ---------------------------------------------------------------------------
__global__ void __launch_bounds__(256) ballq1_smem(
    const float* __restrict__ xyz_all, const float* __restrict__ centers,
    float R2, int* __restrict__ out)
{
    extern __shared__ float sm[];
    float* sx = sm;
    float* sy = sm + N1;
    float* sz = sm + 2 * N1;
    int* buf = (int*)(sm + 3 * N1);          // [8][32]

    const int b = blockIdx.x >> 5;
    const int grp = blockIdx.x & 31;
    const float* xyz = xyz_all + (size_t)b * N1 * 3;
    for (int i = threadIdx.x; i < N1; i += 256) {
        sx[i] = xyz[i * 3 + 0];
        sy[i] = xyz[i * 3 + 1];
        sz[i] = xyz[i * 3 + 2];
    }
    __syncthreads();

    const int wid = threadIdx.x >> 5, lane = threadIdx.x & 31;
    int* mybuf = buf + wid * 32;
    const int s = grp * 8 + wid;                 // center within batch
    const int gw = b * S1 + s;
    const float cx = centers[gw * 3 + 0];
    const float cy = centers[gw * 3 + 1];
    const float cz = centers[gw * 3 + 2];
    int cnt = 0;
    for (int base = 0; base < N1; base += 32) {
        int p = base + lane;
        float dx = sx[p] - cx;
        float dy = sy[p] - cy;
        float dz = sz[p] - cz;
        float d2 = __fadd_rn(__fadd_rn(__fmul_rn(dx, dx), __fmul_rn(dy, dy)),
                             __fmul_rn(dz, dz));
        bool pred = d2 < R2;
        unsigned mask = __ballot_sync(0xffffffffu, pred);
        if (pred) {
            int pos = cnt + __popc(mask & ((1u << lane) - 1u));
            if (pos < NS) mybuf[pos] = p;
        }
        cnt += __popc(mask);
        if (cnt >= NS) break;
    }
    __syncwarp();
    int nv = cnt < NS ? cnt : NS;
    int first = (cnt > 0) ? mybuf[0] : 0;
    int val = (lane < nv) ? mybuf[lane] : first;
    out[(size_t)gw * NS + lane] = val;
}

// ---------------------------------------------------------------------------
// Stage-2 ball query (N=256, cheap): global version, exact
// ---------------------------------------------------------------------------
template <int N>
__global__ void __launch_bounds__(256) ballq_kernel(
    const float* __restrict__ xyz_all, const float* __restrict__ centers,
    int S, float R2, int* __restrict__ out)
{
    const int gw = (blockIdx.x * blockDim.x + threadIdx.x) >> 5;
    const int lane = threadIdx.x & 31;
    const int wl = threadIdx.x >> 5;
    __shared__ int buf[8][32];

    const int b = gw / S;
    const float* xyz = xyz_all + (size_t)b * N * 3;
    const float cx = centers[gw * 3 + 0];
    const float cy = centers[gw * 3 + 1];
    const float cz = centers[gw * 3 + 2];

    int cnt = 0;
    for (int base = 0; base < N; base += 32) {
        int p = base + lane;
        float dx = xyz[p * 3 + 0] - cx;
        float dy = xyz[p * 3 + 1] - cy;
        float dz = xyz[p * 3 + 2] - cz;
        float d2 = __fadd_rn(__fadd_rn(__fmul_rn(dx, dx), __fmul_rn(dy, dy)),
                             __fmul_rn(dz, dz));
        bool pred = d2 < R2;
        unsigned mask = __ballot_sync(0xffffffffu, pred);
        if (pred) {
            int pos = cnt + __popc(mask & ((1u << lane) - 1u));
            if (pos < NS) buf[wl][pos] = p;
        }
        cnt += __popc(mask);
        if (cnt >= NS) break;
    }
    __syncwarp();
    int nv = cnt < NS ? cnt : NS;
    int first = (cnt > 0) ? buf[wl][0] : 0;
    int val = (lane < nv) ? buf[wl][lane] : first;
    out[(size_t)gw * NS + lane] = val;
}

// ---------------------------------------------------------------------------
// Gathers / concat / weight pads
// ---------------------------------------------------------------------------
__global__ void gather1_kernel(const float* __restrict__ data,
                               float* __restrict__ x1)
{
    int r = blockIdx.x * blockDim.x + threadIdx.x;
    if (r >= BB * S1 * NS) return;
    int c = r >> 5;
    int b = c >> 8;
    int g = g_g1[r];
    const float* p = data + ((size_t)b * N1 + g) * 3;
    const float* ctr = g_nx1 + (size_t)c * 3;
    float* o = x1 + (size_t)r * 3;
    o[0] = p[0] - ctr[0];
    o[1] = p[1] - ctr[1];
    o[2] = p[2] - ctr[2];
}

__global__ void gather2_kernel(float* __restrict__ x2)
{
    int r = blockIdx.x * 4 + (threadIdx.x >> 5);
    int lane = threadIdx.x & 31;
    int c = r >> 5;
    int b = c >> 7;
    int j = g_g2[r];
    const float* src = g_nx1 + ((size_t)b * S1 + j) * 3;
    const float* ctr = g_nx2 + (size_t)c * 3;
    const float* f = g_f1 + ((size_t)b * S1 + j) * 128;
    float* dst = x2 + (size_t)r * 160;
    for (int col = lane; col < 160; col += 32)
        dst[col] = (col < 3) ? (src[col] - ctr[col])
                             : (col < 131 ? f[col - 3] : 0.f);
}

__global__ void concat3_kernel(float* __restrict__ x3)
{
    int t = blockIdx.x * blockDim.x + threadIdx.x;
    if (t >= BB * S2 * 288) return;
    int r = t / 288, col = t - r * 288;
    x3[t] = (col < 3) ? g_nx2[(size_t)r * 3 + col]
                      : (col < 259 ? g_f2[(size_t)r * 256 + (col - 3)] : 0.f);
}

__global__ void padw_kernel(const float* __restrict__ w, float* __restrict__ o,
                            int n, int kin, int kout)
{
    int t = blockIdx.x * blockDim.x + threadIdx.x;
    if (t >= n * kout) return;
    int r = t / kout, c = t - r * kout;
    o[t] = (c < kin) ? w[r * kin + c] : 0.f;
}

// ---------------------------------------------------------------------------
// SGEMM for layer 1_0 (K=3, memory-bound)
// ---------------------------------------------------------------------------
__global__ void __launch_bounds__(256) gemm_bias_relu(
    const float* __restrict__ A, const float* __restrict__ W,
    const float* __restrict__ bias, float* __restrict__ C,
    int M, int N, int K, int lda)
{
    __shared__ float As[16][128];
    __shared__ float Ws[16][64];
    const int tid = threadIdx.x;
    const int ty = tid >> 4, tx = tid & 15;
    const int m0 = blockIdx.x * 128;
    const int n0 = blockIdx.y * 64;

    const int a_m = tid >> 1;
    const int a_k0 = (tid & 1) * 8;
    const int w_n = tid >> 2;
    const int w_k0 = (tid & 3) * 4;

    const float* Arow = A + (size_t)(m0 + a_m) * lda;
    const float* Wrow = W + (size_t)(n0 + w_n) * K;

    float acc[8][4];
#pragma unroll
    for (int i = 0; i < 8; i++)
#pragma unroll
        for (int j = 0; j < 4; j++) acc[i][j] = 0.f;

    for (int k0 = 0; k0 < K; k0 += 16) {
#pragma unroll
        for (int i = 0; i < 8; i++) {
            int k = k0 + a_k0 + i;
            As[a_k0 + i][a_m] = (k < K) ? Arow[k] : 0.f;
        }
#pragma unroll
        for (int i = 0; i < 4; i++) {
            int k = k0 + w_k0 + i;
            Ws[w_k0 + i][w_n] = (k < K) ? Wrow[k] : 0.f;
        }
        __syncthreads();
#pragma unroll
        for (int kk = 0; kk < 16; kk++) {
            float a[8], wv[4];
#pragma unroll
            for (int i = 0; i < 8; i++) a[i] = As[kk][ty * 8 + i];
#pragma unroll
            for (int j = 0; j < 4; j++) wv[j] = Ws[kk][tx * 4 + j];
#pragma unroll
            for (int i = 0; i < 8; i++)
#pragma unroll
                for (int j = 0; j < 4; j++)
                    acc[i][j] = fmaf(a[i], wv[j], acc[i][j]);
        }
        __syncthreads();
    }

    float bv[4];
#pragma unroll
    for (int j = 0; j < 4; j++) bv[j] = bias[n0 + tx * 4 + j];
#pragma unroll
    for (int i = 0; i < 8; i++) {
        int m = m0 + ty * 8 + i;
        float4 o;
        o.x = fmaxf(acc[i][0] + bv[0], 0.f);
        o.y = fmaxf(acc[i][1] + bv[1], 0.f);
        o.z = fmaxf(acc[i][2] + bv[2], 0.f);
        o.w = fmaxf(acc[i][3] + bv[3], 0.f);
        *reinterpret_cast<float4*>(C + (size_t)m * N + n0 + tx * 4) = o;
    }
}

// ---------------------------------------------------------------------------
// Shared mma mainloop (macro-free via template): computes acc for one CTA tile.
// CTA tile 128 x BN, BK=32, 256 threads (8 warps, 4x2), warp tile 32 x (BN/2).
// ---------------------------------------------------------------------------
template <int BN, int NTW>
__device__ __forceinline__ void mma_mainloop(
    const float* __restrict__ A, const float* __restrict__ W,
    int K, int m0, int n0, float* smf, uint32_t smbase,
    int tid, int wid, int lane, int g, int tg, int wm, int wn,
    float acc[2][NTW][4])
{
    constexpr int SLOT = (128 + BN) * 36;
    const int KC = K >> 5;

    auto prefetch = [&](int kc, int s) {
        const uint32_t sb = smbase + (uint32_t)(s * SLOT) * 4u;
#pragma unroll
        for (int i = 0; i < 4; i++) {
            int seg = tid + i * 256;
            int r = seg >> 3, c16 = seg & 7;
            cp16(sb + (uint32_t)(r * 36 + c16 * 4) * 4u,
                 A + (size_t)(m0 + r) * K + kc * 32 + c16 * 4);
        }
#pragma unroll
        for (int i = 0; i < BN / 32; i++) {
            int seg = tid + i * 256;
            int r = seg >> 3, c16 = seg & 7;
            cp16(sb + (uint32_t)((128 + r) * 36 + c16 * 4) * 4u,
                 W + (size_t)(n0 + r) * K + kc * 32 + c16 * 4);
        }
    };

    prefetch(0, 0);
    CP_COMMIT();

    for (int kc = 0; kc < KC; kc++) {
        if (kc + 1 < KC) prefetch(kc + 1, (kc + 1) & 1);
        CP_COMMIT();
        CP_WAIT1();
        __syncthreads();

        const float* s_a = smf + (kc & 1) * SLOT;
        const float* s_w = s_a + 128 * 36;

#pragma unroll
        for (int kk = 0; kk < 4; kk++) {
            const int ck = kk * 8 + tg;
            uint32_t ah[2][4], al[2][4];
#pragma unroll
            for (int mt = 0; mt < 2; mt++) {
                int r0 = wm + mt * 16 + g;
                float a0 = s_a[r0 * 36 + ck];
                float a1 = s_a[(r0 + 8) * 36 + ck];
                float a2 = s_a[r0 * 36 + ck + 4];
                float a3 = s_a[(r0 + 8) * 36 + ck + 4];
                float h0 = tf32r(a0), h1 = tf32r(a1);
                float h2 = tf32r(a2), h3 = tf32r(a3);
                ah[mt][0] = __float_as_uint(h0);
                ah[mt][1] = __float_as_uint(h1);
                ah[mt][2] = __float_as_uint(h2);
                ah[mt][3] = __float_as_uint(h3);
                al[mt][0] = __float_as_uint(tf32r(a0 - h0));
                al[mt][1] = __float_as_uint(tf32r(a1 - h1));
                al[mt][2] = __float_as_uint(tf32r(a2 - h2));
                al[mt][3] = __float_as_uint(tf32r(a3 - h3));
            }
#pragma unroll
            for (int nt = 0; nt < NTW; nt++) {
                int n = wn + nt * 8 + g;
                float b0 = s_w[n * 36 + ck];
                float b1 = s_w[n * 36 + ck + 4];
                float hb0 = tf32r(b0), hb1 = tf32r(b1);
                uint32_t bh0 = __float_as_uint(hb0);
                uint32_t bh1 = __float_as_uint(hb1);
                uint32_t bl0 = __float_as_uint(tf32r(b0 - hb0));
                uint32_t bl1 = __float_as_uint(tf32r(b1 - hb1));
#pragma unroll
                for (int mt = 0; mt < 2; mt++) {
                    MMA_TF32(acc[mt][nt], ah[mt], bh0, bh1);
                    MMA_TF32(acc[mt][nt], ah[mt], bl0, bl1);
                    MMA_TF32(acc[mt][nt], al[mt], bh0, bh1);
                }
            }
        }
        __syncthreads();
    }
}

// ---------------------------------------------------------------------------
// Plain GEMM: C = relu(A @ W^T + bias)
// ---------------------------------------------------------------------------
template <int BN>
__global__ void __launch_bounds__(256) gemm_mma(
    const float* __restrict__ A, const float* __restrict__ W,
    const float* __restrict__ bias, float* __restrict__ C,
    int M, int N, int K)
{
    constexpr int NTW = BN / 16;
    extern __shared__ float smf[];
    const int tid = threadIdx.x;
    const int wid = tid >> 5, lane = tid & 31;
    const int g = lane >> 2, tg = lane & 3;
    const int wm = (wid & 3) * 32;
    const int wn = (wid >> 2) * (BN / 2);
    const int m0 = blockIdx.x * 128;
    const int n0 = blockIdx.y * BN;

    float acc[2][NTW][4];
#pragma unroll
    for (int mt = 0; mt < 2; mt++)
#pragma unroll
        for (int nt = 0; nt < NTW; nt++)
#pragma unroll
            for (int j = 0; j < 4; j++) acc[mt][nt][j] = 0.f;

    mma_mainloop<BN, NTW>(A, W, K, m0, n0, smf, smem_u32(smf),
                          tid, wid, lane, g, tg, wm, wn, acc);

#pragma unroll
    for (int mt = 0; mt < 2; mt++) {
#pragma unroll
        for (int nt = 0; nt < NTW; nt++) {
            int row = m0 + wm + mt * 16 + g;
            int col = n0 + wn + nt * 8 + 2 * tg;
            float b0 = __ldg(&bias[col]);
            float b1 = __ldg(&bias[col + 1]);
            float2 o0, o1;
            o0.x = fmaxf(acc[mt][nt][0] + b0, 0.f);
            o0.y = fmaxf(acc[mt][nt][1] + b1, 0.f);
            o1.x = fmaxf(acc[mt][nt][2] + b0, 0.f);
            o1.y = fmaxf(acc[mt][nt][3] + b1, 0.f);
            *reinterpret_cast<float2*>(C + (size_t)row * N + col) = o0;
            *reinterpret_cast<float2*>(C + (size_t)(row + 8) * N + col) = o1;
        }
    }
}

// ---------------------------------------------------------------------------
// GEMM with fused max-pool over groups of PR rows (PR = 32 or 128).
// PR=32 : dst[center][col] = relu(max over 32 rows + bias), center = row/32.
// PR=128: dst[blockIdx.x * N + col] (one batch per M-tile).
// Exact: max commutes with +bias (per-col) and relu (monotone).
// ---------------------------------------------------------------------------
template <int BN, int PR>
__global__ void __launch_bounds__(256) gemm_mma_pool(
    const float* __restrict__ A, const float* __restrict__ W,
    const float* __restrict__ bias, float* __restrict__ dst,
    int M, int N, int K)
{
    constexpr int NTW = BN / 16;
    extern __shared__ float smf[];
    __shared__ float sbuf[4][BN];      // only used for PR=128
    const int tid = threadIdx.x;
    const int wid = tid >> 5, lane = tid & 31;
    const int g = lane >> 2, tg = lane & 3;
    const int wm = (wid & 3) * 32;
    const int wn = (wid >> 2) * (BN / 2);
    const int m0 = blockIdx.x * 128;
    const int n0 = blockIdx.y * BN;

    float acc[2][NTW][4];
#pragma unroll
    for (int mt = 0; mt < 2; mt++)
#pragma unroll
        for (int nt = 0; nt < NTW; nt++)
#pragma unroll
            for (int j = 0; j < 4; j++) acc[mt][nt][j] = 0.f;

    mma_mainloop<BN, NTW>(A, W, K, m0, n0, smf, smem_u32(smf),
                          tid, wid, lane, g, tg, wm, wn, acc);

    // Per-warp max over the warp's 32 rows (one ball group).
#pragma unroll
    for (int nt = 0; nt < NTW; nt++) {
        float v0 = fmaxf(fmaxf(acc[0][nt][0], acc[0][nt][2]),
                         fmaxf(acc[1][nt][0], acc[1][nt][2]));
        float v1 = fmaxf(fmaxf(acc[0][nt][1], acc[0][nt][3]),
                         fmaxf(acc[1][nt][1], acc[1][nt][3]));
#pragma unroll
        for (int off = 4; off < 32; off <<= 1) {
            v0 = fmaxf(v0, __shfl_xor_sync(0xffffffffu, v0, off));
            v1 = fmaxf(v1, __shfl_xor_sync(0xffffffffu, v1, off));
        }
        if (g == 0) {
            int lcol = wn + nt * 8 + 2 * tg;
            if (PR == 32) {
                int center = blockIdx.x * 4 + (wid & 3);
                int col = n0 + lcol;
                dst[(size_t)center * N + col] =
                    fmaxf(v0 + __ldg(&bias[col]), 0.f);
                dst[(size_t)center * N + col + 1] =
                    fmaxf(v1 + __ldg(&bias[col + 1]), 0.f);
            } else {
                sbuf[wid & 3][lcol] = v0;
                sbuf[wid & 3][lcol + 1] = v1;
            }
        }
    }
    if (PR == 128) {
        __syncthreads();
        if (tid < BN) {
            float m = fmaxf(fmaxf(sbuf[0][tid], sbuf[1][tid]),
                            fmaxf(sbuf[2][tid], sbuf[3][tid]));
            int col = n0 + tid;
            dst[(size_t)blockIdx.x * N + col] =
                fmaxf(m + __ldg(&bias[col]), 0.f);
        }
    }
}

// ---------------------------------------------------------------------------
static void run_mma(const float* A, const float* W, const float* bias,
                    float* C, int M, int N, int K)
{
    if (N % 128 == 0) {
        const int smem = 2 * (128 + 128) * 36 * 4;   // 73728
        cudaFuncSetAttribute(gemm_mma<128>,
                             cudaFuncAttributeMaxDynamicSharedMemorySize, smem);
        dim3 g(M / 128, N / 128);
        gemm_mma<128><<<g, 256, smem>>>(A, W, bias, C, M, N, K);
    } else {
        const int smem = 2 * (128 + 64) * 36 * 4;    // 55296
        cudaFuncSetAttribute(gemm_mma<64>,
                             cudaFuncAttributeMaxDynamicSharedMemorySize, smem);
        dim3 g(M / 128, N / 64);
        gemm_mma<64><<<g, 256, smem>>>(A, W, bias, C, M, N, K);
    }
}

template <int PR>
static void run_mma_pool(const float* A, const float* W, const float* bias,
                         float* dst, int M, int N, int K)
{
    const int smem = 2 * (128 + 128) * 36 * 4;       // 73728
    cudaFuncSetAttribute(gemm_mma_pool<128, PR>,
                         cudaFuncAttributeMaxDynamicSharedMemorySize, smem);
    dim3 g(M / 128, N / 128);
    gemm_mma_pool<128, PR><<<g, 256, smem>>>(A, W, bias, dst, M, N, K);
}

extern "C" void kernel_launch(void* const* d_in, const int* in_sizes, int n_in,
                              void* d_out, int out_size)
{
    (void)in_sizes; (void)n_in; (void)out_size;
    const float* data = (const float*)d_in[0];
    const float *w[9], *bi[9];
    for (int i = 0; i < 9; i++) {
        w[i]  = (const float*)d_in[1 + 2 * i];
        bi[i] = (const float*)d_in[2 + 2 * i];
    }

    float *scr0, *scr1, *f1, *f2, *nx1, *nx2, *x3, *w2p, *w3p;
    int *g1, *g2;
    cudaGetSymbolAddress((void**)&scr0, g_scr0);
    cudaGetSymbolAddress((void**)&scr1, g_scr1);
    cudaGetSymbolAddress((void**)&f1, g_f1);
    cudaGetSymbolAddress((void**)&f2, g_f2);
    cudaGetSymbolAddress((void**)&nx1, g_nx1);
    cudaGetSymbolAddress((void**)&nx2, g_nx2);
    cudaGetSymbolAddress((void**)&g1, g_g1);
    cudaGetSymbolAddress((void**)&g2, g_g2);
    cudaGetSymbolAddress((void**)&x3, g_x3);
    cudaGetSymbolAddress((void**)&w2p, g_w2p);
    cudaGetSymbolAddress((void**)&w3p, g_w3p);

    const float R2a = (float)(0.2 * 0.2);
    const float R2b = (float)(0.4 * 0.4);

    padw_kernel<<<(128 * 160 + 255) / 256, 256>>>(w[3], w2p, 128, 131, 160);
    padw_kernel<<<(256 * 288 + 255) / 256, 256>>>(w[6], w3p, 256, 259, 288);

    // ---- Stage 1 ----
    fps_kernel<N1, S1, 512><<<BB, 512>>>(data, nx1);
    {
        const int smem = 3 * N1 * 4 + 8 * 32 * 4;   // 50176
        cudaFuncSetAttribute(ballq1_smem,
                             cudaFuncAttributeMaxDynamicSharedMemorySize, smem);
        ballq1_smem<<<BB * 32, 256, smem>>>(data, nx1, R2a, g1);
    }
    gather1_kernel<<<(BB * S1 * NS + 255) / 256, 256>>>(data, scr1);
    {
        dim3 g((BB * S1 * NS) / 128, 1);
        gemm_bias_relu<<<g, 256>>>(scr1, w[0], bi[0], scr0, BB * S1 * NS, 64, 3, 3);
    }
    run_mma(scr0, w[1], bi[1], scr1, BB * S1 * NS, 64, 64);
    run_mma_pool<32>(scr1, w[2], bi[2], f1, BB * S1 * NS, 128, 64);

    // ---- Stage 2 ----
    fps_kernel<S1, S2, 256><<<BB, 256>>>(nx1, nx2);
    ballq_kernel<S1><<<(BB * S2) / 8, 256>>>(nx1, nx2, S2, R2b, g2);
    gather2_kernel<<<(BB * S2 * NS) / 4, 128>>>(scr0);
    run_mma(scr0, w2p, bi[3], scr1, BB * S2 * NS, 128, 160);
    run_mma(scr1, w[4], bi[4], scr0, BB * S2 * NS, 128, 128);
    run_mma_pool<32>(scr0, w[5], bi[5], f2, BB * S2 * NS, 256, 128);

    // ---- Stage 3 ----
    concat3_kernel<<<(BB * S2 * 288 + 255) / 256, 256>>>(x3);
    run_mma(x3, w3p, bi[6], scr0, BB * S2, 256, 288);
    run_mma(scr0, w[7], bi[7], scr1, BB * S2, 512, 256);
    run_mma_pool<128>(scr1, w[8], bi[8], (float*)d_out, BB * S2, 1024, 512);
}